// round 1
// baseline (speedup 1.0000x reference)
#include <cuda_runtime.h>

// ---------------------------------------------------------------------------
// Allegro-style GNN layer, fp32, sm_103a.
// Pipeline:
//   k_zero : zero env accumulators + output
//   k1     : geometry + bessel + 2-body MLP (40->64->128->128) + Wenv0, scatter env
//   k2a    : channel products (p0..p4), s_mix, v_mix, scal0
//   k2b    : lat-update MLP (192->128->128) + residual + Wenv1, scatter env1
//   k3     : q0/q1 + final MLP (192->128->128) + residual, scatter node_out
// Warp-per-edge-group (EPW edges/warp), weights resident in shared memory,
// lane == channel (M = 32) for all equivariant math.
// ---------------------------------------------------------------------------

#define NN 10000
#define NE 320000

__device__ float g_lat  [NE * 128];
__device__ float g_wedge[NE * 64];
__device__ float g_scal0[NE * 64];
__device__ float g_smix [NE * 32];
__device__ float g_vmix [NE * 96];
__device__ float g_Y    [NE * 4];
__device__ float g_fcut [NE];
__device__ float g_env  [NN * 128];
__device__ float g_env1 [NN * 128];

__device__ __constant__ float kRS40  = 0.15811388300841897f;  // 1/sqrt(40)
__device__ __constant__ float kRS64  = 0.125f;                // 1/sqrt(64)
__device__ __constant__ float kRS96  = 0.10206207261596575f;  // 1/sqrt(96)
__device__ __constant__ float kRS128 = 0.08838834764831845f;  // 1/sqrt(128)
__device__ __constant__ float kRS192 = 0.07216878364870323f;  // 1/sqrt(192)

#define F_ISN       0.17677669529663689f   // 1/sqrt(32)
#define F_SQRT3     1.7320508075688772f
#define F_INV_SQRT3 0.5773502691896258f
#define F_INV_SQRT2 0.7071067811865476f
#define F_C_OLD     0.8944271909999159f    // 1/sqrt(1.25)
#define F_C_NEW     0.4472135954999579f    // 0.5/sqrt(1.25)
#define F_BESSEL    0.6324555320336759f    // sqrt(2/5)
#define F_PI        3.14159265358979323846f
#define F_INV_RMAX  0.2f

// ---------------------------------------------------------------------------
// Warp-cooperative mat-vec: y[OUT] = act( scale_e * (x[IN] @ W[IN][OUT]) )
// W in shared (row-major), x/y per-edge in shared. Lane owns OUT/32 outputs
// (consecutive -> vector LDS of W rows). EPW edges amortize the W loads.
// ---------------------------------------------------------------------------
template <int IN, int OUT, int EPW, bool SILU>
__device__ __forceinline__ void warp_matvec(
    const float* __restrict__ Wsh,
    const float* __restrict__ xsh, int xstride,
    float*       __restrict__ ysh, int ystride,
    const float* scales, int lane)
{
    constexpr int OPL = OUT / 32;
    float acc[EPW][OPL];
#pragma unroll
    for (int e = 0; e < EPW; e++)
#pragma unroll
        for (int k = 0; k < OPL; k++) acc[e][k] = 0.0f;

#pragma unroll 4
    for (int i = 0; i < IN; i++) {
        float w[OPL];
        if constexpr (OPL == 4) {
            float4 wv = *reinterpret_cast<const float4*>(Wsh + i * OUT + 4 * lane);
            w[0] = wv.x; w[1] = wv.y; w[2] = wv.z; w[3] = wv.w;
        } else if constexpr (OPL == 2) {
            float2 wv = *reinterpret_cast<const float2*>(Wsh + i * OUT + 2 * lane);
            w[0] = wv.x; w[1] = wv.y;
        } else {
            w[0] = Wsh[i * OUT + lane];
        }
#pragma unroll
        for (int e = 0; e < EPW; e++) {
            float xi = xsh[e * xstride + i];
#pragma unroll
            for (int k = 0; k < OPL; k++) acc[e][k] = fmaf(xi, w[k], acc[e][k]);
        }
    }
#pragma unroll
    for (int e = 0; e < EPW; e++) {
#pragma unroll
        for (int k = 0; k < OPL; k++) {
            float v = acc[e][k] * scales[e];
            if (SILU) v = v * __frcp_rn(1.0f + __expf(-v));
            ysh[e * ystride + OPL * lane + k] = v;
        }
    }
    __syncwarp();
}

// ---------------------------------------------------------------------------
__global__ void k_zero(float* __restrict__ out)
{
    int i = blockIdx.x * blockDim.x + threadIdx.x;
    int stride = gridDim.x * blockDim.x;
    for (; i < NN * 128; i += stride) {
        g_env[i]  = 0.0f;
        g_env1[i] = 0.0f;
        out[i]    = 0.0f;
    }
}

// ---------------------------------------------------------------------------
// K1: geometry + 2-body MLP + Wenv0 + env scatter
// ---------------------------------------------------------------------------
template <int EPW>
__global__ void __launch_bounds__(256, 1) k1(
    const float* __restrict__ coords, const float* __restrict__ attrs,
    const int*   __restrict__ eidx,
    const float* __restrict__ W2b0, const float* __restrict__ W2b1,
    const float* __restrict__ W2b2, const float* __restrict__ Wenv0)
{
    extern __shared__ float sh[];
    float* sW0  = sh;                   // 40*64   = 2560
    float* sW1  = sW0 + 2560;           // 64*128  = 8192
    float* sW2  = sW1 + 8192;           // 128*128 = 16384
    float* sWe  = sW2 + 16384;          // 128*128 = 16384
    float* sbuf = sWe + 16384;

    int tid = threadIdx.x;
    for (int i = tid; i < 2560;  i += 256) sW0[i] = W2b0[i];
    for (int i = tid; i < 8192;  i += 256) sW1[i] = W2b1[i];
    for (int i = tid; i < 16384; i += 256) { sW2[i] = W2b2[i]; sWe[i] = Wenv0[i]; }
    __syncthreads();

    int warp = tid >> 5, lane = tid & 31;
    float* xb = sbuf + warp * (EPW * 256);
    float* yb = xb + EPW * 128;
    int nwarp = gridDim.x * 8;
    int gw = blockIdx.x * 8 + warp;

    float sA[EPW], sB[EPW], sC[EPW], sD[EPW];
#pragma unroll
    for (int j = 0; j < EPW; j++) { sA[j] = kRS40; sB[j] = kRS64; sD[j] = kRS128; }

    for (int base = gw * EPW; base < NE; base += nwarp * EPW) {
        int   ctr[EPW];
        float fc[EPW], Y1[EPW], Y2[EPW], Y3[EPW];
#pragma unroll
        for (int j = 0; j < EPW; j++) {
            int e = base + j; if (e >= NE) e = NE - 1;
            int snd = eidx[e];
            int c   = eidx[NE + e];
            ctr[j] = c;
            float dx = coords[c * 3 + 0] - coords[snd * 3 + 0];
            float dy = coords[c * 3 + 1] - coords[snd * 3 + 1];
            float dz = coords[c * 3 + 2] - coords[snd * 3 + 2];
            float r2 = dx * dx + dy * dy + dz * dz + 1e-12f;
            float r  = sqrtf(r2);
            float inv_r = 1.0f / r;
            float u  = r * F_INV_RMAX;
            float u2 = u * u, u3 = u2 * u, u6 = u3 * u3, u7 = u6 * u, u8 = u7 * u;
            float f  = 1.0f - 28.0f * u6 + 48.0f * u7 - 21.0f * u8;
            if (u >= 1.0f) f = 0.0f;
            fc[j] = f;
            Y1[j] = F_SQRT3 * dx * inv_r;
            Y2[j] = F_SQRT3 * dy * inv_r;
            Y3[j] = F_SQRT3 * dz * inv_r;
            if (lane < 16) xb[j * 128 + lane] = attrs[c * 16 + lane];
            else           xb[j * 128 + lane] = attrs[snd * 16 + (lane - 16)];
            if (lane < 8) {
                float b = F_BESSEL * sinf((lane + 1) * F_PI * u) * inv_r * f;
                xb[j * 128 + 32 + lane] = b;
            }
            sC[j] = kRS128 * f;  // fold fcut into layer-2 scale
        }
        __syncwarp();

        warp_matvec<40, 64,  EPW, true >(sW0, xb, 128, yb, 128, sA, lane);
        warp_matvec<64, 128, EPW, true >(sW1, yb, 128, xb, 128, sB, lane);
        warp_matvec<128,128, EPW, false>(sW2, xb, 128, yb, 128, sC, lane); // lat (xfcut)
        warp_matvec<128,128, EPW, false>(sWe, yb, 128, xb, 128, sD, lane); // w_all

#pragma unroll
        for (int j = 0; j < EPW; j++) {
            int e = base + j;
            if (e >= NE) break;
            float4 lv = *reinterpret_cast<float4*>(&yb[j * 128 + 4 * lane]);
            *reinterpret_cast<float4*>(&g_lat[(long)e * 128 + 4 * lane]) = lv;
            float we0 = xb[j * 128 + 2 * lane];
            float we1 = xb[j * 128 + 2 * lane + 1];
            g_wedge[e * 64 + 2 * lane]     = we0;
            g_wedge[e * 64 + 2 * lane + 1] = we1;
            float wv0 = xb[j * 128 + 64 + 2 * lane];
            float wv1 = xb[j * 128 + 64 + 2 * lane + 1];
            float* dst = &g_env[(long)ctr[j] * 128 + 4 * lane];
            atomicAdd(dst + 0, wv0);
            atomicAdd(dst + 1, wv1 * Y1[j]);
            atomicAdd(dst + 2, wv1 * Y2[j]);
            atomicAdd(dst + 3, wv1 * Y3[j]);
            if (lane == 0) {
                g_fcut[e]      = fc[j];
                g_Y[e * 4 + 0] = 1.0f;
                g_Y[e * 4 + 1] = Y1[j];
                g_Y[e * 4 + 2] = Y2[j];
                g_Y[e * 4 + 3] = Y3[j];
            }
        }
        __syncwarp();
    }
}

// ---------------------------------------------------------------------------
// K2a: equivariant products + s_mix + v_mix + scal0 (lane == channel m)
// ---------------------------------------------------------------------------
__global__ void __launch_bounds__(256) k2a(
    const int* __restrict__ eidx,
    const float* __restrict__ Ws0, const float* __restrict__ Wv0)
{
    __shared__ float sWs[64 * 32];
    __shared__ float sWv[96 * 32];
    __shared__ float stage[8][64];
    __shared__ float Pst[8][96 * 4];

    int tid = threadIdx.x;
    for (int i = tid; i < 64 * 32; i += 256) sWs[i] = Ws0[i];
    for (int i = tid; i < 96 * 32; i += 256) sWv[i] = Wv0[i];
    __syncthreads();

    int warp = tid >> 5, lane = tid & 31;
    int gw = blockIdx.x * 8 + warp;
    int nw = gridDim.x * 8;

    for (int e = gw; e < NE; e += nw) {
        int c = eidx[NE + e];
        float2 we = *reinterpret_cast<const float2*>(&g_wedge[e * 64 + 2 * lane]);
        float4 en = *reinterpret_cast<const float4*>(&g_env[(long)c * 128 + 4 * lane]);
        float4 Yv = *reinterpret_cast<const float4*>(&g_Y[e * 4]);
        float fs  = we.x;
        float fv0 = we.y * Yv.y, fv1 = we.y * Yv.z, fv2 = we.y * Yv.w;
        float es  = en.x * F_ISN;
        float ev0 = en.y * F_ISN, ev1 = en.z * F_ISN, ev2 = en.w * F_ISN;

        float p0 = fs * es;
        float p1 = (fv0 * ev0 + fv1 * ev1 + fv2 * ev2) * F_INV_SQRT3;
        stage[warp][lane]      = p0;
        stage[warp][32 + lane] = p1;
        float* P = Pst[warp];
        P[lane * 4 + 0] = fs * ev0;
        P[lane * 4 + 1] = fs * ev1;
        P[lane * 4 + 2] = fs * ev2;
        P[(32 + lane) * 4 + 0] = fv0 * es;
        P[(32 + lane) * 4 + 1] = fv1 * es;
        P[(32 + lane) * 4 + 2] = fv2 * es;
        P[(64 + lane) * 4 + 0] = (fv1 * ev2 - fv2 * ev1) * F_INV_SQRT2;
        P[(64 + lane) * 4 + 1] = (fv2 * ev0 - fv0 * ev2) * F_INV_SQRT2;
        P[(64 + lane) * 4 + 2] = (fv0 * ev1 - fv1 * ev0) * F_INV_SQRT2;
        __syncwarp();

        float sm = 0.0f;
#pragma unroll 4
        for (int i = 0; i < 64; i++) sm = fmaf(stage[warp][i], sWs[i * 32 + lane], sm);
        sm *= kRS64;

        float v0 = 0.0f, v1 = 0.0f, v2 = 0.0f;
#pragma unroll 4
        for (int i = 0; i < 96; i++) {
            float w = sWv[i * 32 + lane];
            v0 = fmaf(P[i * 4 + 0], w, v0);
            v1 = fmaf(P[i * 4 + 1], w, v1);
            v2 = fmaf(P[i * 4 + 2], w, v2);
        }
        v0 *= kRS96; v1 *= kRS96; v2 *= kRS96;

        g_scal0[e * 64 + lane]      = p0;
        g_scal0[e * 64 + 32 + lane] = p1;
        g_smix[e * 32 + lane] = sm;
        g_vmix[e * 96 + 3 * lane + 0] = v0;
        g_vmix[e * 96 + 3 * lane + 1] = v1;
        g_vmix[e * 96 + 3 * lane + 2] = v2;
        __syncwarp();
    }
}

// ---------------------------------------------------------------------------
// K2b: lat update MLP (192->128->128) + residual + Wenv1 + env1 scatter
// per-edge shared layout: x[0..191], h[192..319], nl[320..447]  (stride 448)
// ---------------------------------------------------------------------------
template <int EPW>
__global__ void __launch_bounds__(256, 1) k2b(
    const int*   __restrict__ eidx,
    const float* __restrict__ Wlat0, const float* __restrict__ Wlat1,
    const float* __restrict__ Wenv1)
{
    extern __shared__ float sh[];
    float* sL0  = sh;             // 192*128 = 24576
    float* sL1  = sL0 + 24576;    // 128*128 = 16384
    float* sE1  = sL1 + 16384;    // 128*64  = 8192
    float* sbuf = sE1 + 8192;

    int tid = threadIdx.x;
    for (int i = tid; i < 24576; i += 256) sL0[i] = Wlat0[i];
    for (int i = tid; i < 16384; i += 256) sL1[i] = Wlat1[i];
    for (int i = tid; i < 8192;  i += 256) sE1[i] = Wenv1[i];
    __syncthreads();

    int warp = tid >> 5, lane = tid & 31;
    float* xb = sbuf + warp * (EPW * 448);
    int nw = gridDim.x * 8;
    int gw = blockIdx.x * 8 + warp;

    float s0[EPW], s1[EPW], s2[EPW];
    int ctr[EPW];
    float Yy[EPW], Yz[EPW], Yw[EPW];

    for (int base = gw * EPW; base < NE; base += nw * EPW) {
#pragma unroll
        for (int j = 0; j < EPW; j++) {
            int e = base + j; if (e >= NE) e = NE - 1;
            ctr[j] = eidx[NE + e];
            float f = g_fcut[e];
            float4 Yv = *reinterpret_cast<const float4*>(&g_Y[e * 4]);
            Yy[j] = Yv.y; Yz[j] = Yv.z; Yw[j] = Yv.w;
            float* x = xb + j * 448;
            float4 lv = *reinterpret_cast<const float4*>(&g_lat[(long)e * 128 + 4 * lane]);
            *reinterpret_cast<float4*>(&x[4 * lane]) = lv;
            x[128 + lane]      = g_scal0[e * 64 + lane];
            x[128 + 32 + lane] = g_scal0[e * 64 + 32 + lane];
            s0[j] = kRS192;
            s1[j] = kRS128 * f;
            s2[j] = kRS128;
        }
        __syncwarp();

        warp_matvec<192, 128, EPW, true >(sL0, xb + 0,   448, xb + 192, 448, s0, lane);
        warp_matvec<128, 128, EPW, false>(sL1, xb + 192, 448, xb + 320, 448, s1, lane);

        // residual: lat = c_old*lat + c_new*new_lat
#pragma unroll
        for (int j = 0; j < EPW; j++) {
            float* x = xb + j * 448;
            float4 lv = *reinterpret_cast<float4*>(&x[4 * lane]);
            float4 nl = *reinterpret_cast<float4*>(&x[320 + 4 * lane]);
            lv.x = F_C_OLD * lv.x + F_C_NEW * nl.x;
            lv.y = F_C_OLD * lv.y + F_C_NEW * nl.y;
            lv.z = F_C_OLD * lv.z + F_C_NEW * nl.z;
            lv.w = F_C_OLD * lv.w + F_C_NEW * nl.w;
            *reinterpret_cast<float4*>(&x[4 * lane]) = lv;
            int e = base + j;
            if (e < NE)
                *reinterpret_cast<float4*>(&g_lat[(long)e * 128 + 4 * lane]) = lv;
        }
        __syncwarp();

        // w_env1 = lat @ Wenv1 (128 -> 64), into the h region
        warp_matvec<128, 64, EPW, false>(sE1, xb + 0, 448, xb + 192, 448, s2, lane);

#pragma unroll
        for (int j = 0; j < EPW; j++) {
            int e = base + j;
            if (e >= NE) break;
            float* x  = xb + j * 448;
            float w0  = x[192 + 2 * lane];
            float w1  = x[192 + 2 * lane + 1];
            float* dst = &g_env1[(long)ctr[j] * 128 + 4 * lane];
            atomicAdd(dst + 0, w0);
            atomicAdd(dst + 1, w1 * Yy[j]);
            atomicAdd(dst + 2, w1 * Yz[j]);
            atomicAdd(dst + 3, w1 * Yw[j]);
        }
        __syncwarp();
    }
}

// ---------------------------------------------------------------------------
// K3: q0/q1 + final MLP + residual + node_out scatter
// ---------------------------------------------------------------------------
template <int EPW>
__global__ void __launch_bounds__(256, 1) k3(
    const int*   __restrict__ eidx,
    const float* __restrict__ Wfin0, const float* __restrict__ Wfin1,
    float* __restrict__ out)
{
    extern __shared__ float sh[];
    float* sF0  = sh;             // 192*128 = 24576
    float* sF1  = sF0 + 24576;    // 128*128 = 16384
    float* sbuf = sF1 + 16384;

    int tid = threadIdx.x;
    for (int i = tid; i < 24576; i += 256) sF0[i] = Wfin0[i];
    for (int i = tid; i < 16384; i += 256) sF1[i] = Wfin1[i];
    __syncthreads();

    int warp = tid >> 5, lane = tid & 31;
    float* xb = sbuf + warp * (EPW * 448);
    int nw = gridDim.x * 8;
    int gw = blockIdx.x * 8 + warp;

    float s0[EPW], s1[EPW];
    int ctr[EPW];

    for (int base = gw * EPW; base < NE; base += nw * EPW) {
#pragma unroll
        for (int j = 0; j < EPW; j++) {
            int e = base + j; if (e >= NE) e = NE - 1;
            int c = eidx[NE + e];
            ctr[j] = c;
            float f = g_fcut[e];
            float4 e1 = *reinterpret_cast<const float4*>(&g_env1[(long)c * 128 + 4 * lane]);
            float es  = e1.x * F_ISN;
            float ev0 = e1.y * F_ISN, ev1 = e1.z * F_ISN, ev2 = e1.w * F_ISN;
            float sm  = g_smix[e * 32 + lane];
            float v0  = g_vmix[e * 96 + 3 * lane + 0];
            float v1  = g_vmix[e * 96 + 3 * lane + 1];
            float v2  = g_vmix[e * 96 + 3 * lane + 2];
            float q0  = sm * es;
            float q1  = (v0 * ev0 + v1 * ev1 + v2 * ev2) * F_INV_SQRT3;
            float* x = xb + j * 448;
            float4 lv = *reinterpret_cast<const float4*>(&g_lat[(long)e * 128 + 4 * lane]);
            *reinterpret_cast<float4*>(&x[4 * lane]) = lv;
            x[128 + lane] = q0;
            x[160 + lane] = q1;
            s0[j] = kRS192;
            s1[j] = kRS128 * f;
        }
        __syncwarp();

        warp_matvec<192, 128, EPW, true >(sF0, xb + 0,   448, xb + 192, 448, s0, lane);
        warp_matvec<128, 128, EPW, false>(sF1, xb + 192, 448, xb + 320, 448, s1, lane);

#pragma unroll
        for (int j = 0; j < EPW; j++) {
            int e = base + j;
            if (e >= NE) break;
            float* x = xb + j * 448;
            float4 lv = *reinterpret_cast<float4*>(&x[4 * lane]);
            float4 nl = *reinterpret_cast<float4*>(&x[320 + 4 * lane]);
            float o0 = (F_C_OLD * lv.x + F_C_NEW * nl.x) * F_ISN;
            float o1 = (F_C_OLD * lv.y + F_C_NEW * nl.y) * F_ISN;
            float o2 = (F_C_OLD * lv.z + F_C_NEW * nl.z) * F_ISN;
            float o3 = (F_C_OLD * lv.w + F_C_NEW * nl.w) * F_ISN;
            float* dst = &out[(long)ctr[j] * 128 + 4 * lane];
            atomicAdd(dst + 0, o0);
            atomicAdd(dst + 1, o1);
            atomicAdd(dst + 2, o2);
            atomicAdd(dst + 3, o3);
        }
        __syncwarp();
    }
}

// ---------------------------------------------------------------------------
extern "C" void kernel_launch(void* const* d_in, const int* in_sizes, int n_in,
                              void* d_out, int out_size)
{
    const float* coords = (const float*)d_in[0];
    const float* attrs  = (const float*)d_in[1];
    const int*   eidx   = (const int*)  d_in[2];
    const float* W2b0   = (const float*)d_in[3];
    const float* W2b1   = (const float*)d_in[4];
    const float* W2b2   = (const float*)d_in[5];
    const float* Wenv0  = (const float*)d_in[6];
    const float* Wlat0  = (const float*)d_in[7];
    const float* Wlat1  = (const float*)d_in[8];
    const float* Ws0    = (const float*)d_in[9];
    const float* Wv0    = (const float*)d_in[10];
    const float* Wenv1  = (const float*)d_in[11];
    const float* Wfin0  = (const float*)d_in[12];
    const float* Wfin1  = (const float*)d_in[13];
    float* out = (float*)d_out;

    const size_t smem1  = (size_t)(43520 + 8 * 4 * 256) * sizeof(float); // 206848
    const size_t smem2b = (size_t)(49152 + 8 * 2 * 448) * sizeof(float); // 225280
    const size_t smem3  = (size_t)(40960 + 8 * 4 * 448) * sizeof(float); // 221184

    cudaFuncSetAttribute(k1<4>,  cudaFuncAttributeMaxDynamicSharedMemorySize, (int)smem1);
    cudaFuncSetAttribute(k2b<2>, cudaFuncAttributeMaxDynamicSharedMemorySize, (int)smem2b);
    cudaFuncSetAttribute(k3<4>,  cudaFuncAttributeMaxDynamicSharedMemorySize, (int)smem3);

    k_zero<<<512, 256>>>(out);
    k1<4><<<148, 256, smem1>>>(coords, attrs, eidx, W2b0, W2b1, W2b2, Wenv0);
    k2a<<<592, 256>>>(eidx, Ws0, Wv0);
    k2b<2><<<148, 256, smem2b>>>(eidx, Wlat0, Wlat1, Wenv1);
    k3<4><<<148, 256, smem3>>>(eidx, Wfin0, Wfin1, out);
}